// round 1
// baseline (speedup 1.0000x reference)
#include <cuda_runtime.h>
#include <cstdint>
#include <math.h>

// Problem dims (fixed by reference)
#define LSEQ 2048
#define BATCH 8
#define DIM 1024
#define MROWS (LSEQ * BATCH)   // 16384
#define NCOLS (3 * DIM)        // 3072
#define KDIM  DIM              // 1024
#define LN_EPS 1e-5f

// Scratch (static device globals: allocation-free per harness rules)
__device__ float g_xnorm[(size_t)MROWS * DIM];        // 64 MB
__device__ float g_ufr[(size_t)MROWS * NCOLS];        // 192 MB (activated u,f,r)

// ---------------------------------------------------------------------------
// Kernel 1: LayerNorm. One block per (l,b) row, 256 threads, float4 per thread.
// ---------------------------------------------------------------------------
__global__ void __launch_bounds__(256) sru_ln(const float* __restrict__ x,
                                              const float* __restrict__ ln_g,
                                              const float* __restrict__ ln_b) {
    __shared__ float red_s[8];
    __shared__ float red_ss[8];
    const int row = blockIdx.x;
    const int t = threadIdx.x;

    float4 a = ((const float4*)(x + (size_t)row * DIM))[t];
    float s  = a.x + a.y + a.z + a.w;
    float ss = a.x * a.x + a.y * a.y + a.z * a.z + a.w * a.w;
    #pragma unroll
    for (int o = 16; o > 0; o >>= 1) {
        s  += __shfl_xor_sync(0xFFFFFFFFu, s, o);
        ss += __shfl_xor_sync(0xFFFFFFFFu, ss, o);
    }
    if ((t & 31) == 0) { red_s[t >> 5] = s; red_ss[t >> 5] = ss; }
    __syncthreads();
    float ts = 0.f, tss = 0.f;
    #pragma unroll
    for (int i = 0; i < 8; i++) { ts += red_s[i]; tss += red_ss[i]; }

    const float mu   = ts * (1.0f / DIM);
    const float var  = tss * (1.0f / DIM) - mu * mu;
    const float rstd = rsqrtf(var + LN_EPS);

    float4 g = ((const float4*)ln_g)[t];
    float4 b = ((const float4*)ln_b)[t];
    float4 o;
    o.x = (a.x - mu) * rstd * g.x + b.x;
    o.y = (a.y - mu) * rstd * g.y + b.y;
    o.z = (a.z - mu) * rstd * g.z + b.z;
    o.w = (a.w - mu) * rstd * g.w + b.w;
    ((float4*)(g_xnorm + (size_t)row * DIM))[t] = o;
}

// ---------------------------------------------------------------------------
// Kernel 2: GEMM ufr = xnorm @ W^T + b, fused activations.
// tf32x3 split on mma.sync.m16n8k8 for ~fp32 accuracy on tensor pipes.
// BM=128 BN=128 BK=16, 256 threads = 8 warps (2 x M, 4 x N), warp tile 64x32.
// ---------------------------------------------------------------------------
__device__ __forceinline__ void split_tf32(float v, uint32_t& hi, uint32_t& lo) {
    asm("cvt.rna.tf32.f32 %0, %1;" : "=r"(hi) : "f"(v));
    float r = v - __uint_as_float(hi);
    asm("cvt.rna.tf32.f32 %0, %1;" : "=r"(lo) : "f"(r));
}

__device__ __forceinline__ void mma_tf32(float* d, const uint32_t* a, const uint32_t* b) {
    asm volatile(
        "mma.sync.aligned.m16n8k8.row.col.f32.tf32.tf32.f32 "
        "{%0,%1,%2,%3}, {%4,%5,%6,%7}, {%8,%9}, {%0,%1,%2,%3};\n"
        : "+f"(d[0]), "+f"(d[1]), "+f"(d[2]), "+f"(d[3])
        : "r"(a[0]), "r"(a[1]), "r"(a[2]), "r"(a[3]), "r"(b[0]), "r"(b[1]));
}

__device__ __forceinline__ float sru_act(float v, int n) {
    // cols [0,D): u -> tanh ; [D,3D): f,r -> sigmoid
    if (n < DIM) return tanhf(v);
    return 1.0f / (1.0f + expf(-v));
}

__global__ void __launch_bounds__(256, 1) sru_gemm(const float* __restrict__ W,
                                                   const float* __restrict__ bias) {
    __shared__ float As[128][20];   // padded stride 20 -> conflict-free frag loads
    __shared__ float Bs[128][20];

    const int tid  = threadIdx.x;
    const int lane = tid & 31;
    const int warp = tid >> 5;
    const int wm   = (warp & 1) << 6;   // 0 / 64
    const int wn   = (warp >> 1) << 5;  // 0..96
    const int bm   = blockIdx.y << 7;
    const int bn   = blockIdx.x << 7;
    const int grp  = lane >> 2;         // 0..7
    const int tig  = lane & 3;          // 0..3

    float acc[4][4][4];
    #pragma unroll
    for (int i = 0; i < 4; i++)
        #pragma unroll
        for (int j = 0; j < 4; j++)
            #pragma unroll
            for (int e = 0; e < 4; e++) acc[i][j][e] = 0.0f;

    const int lr = tid >> 2;            // 0..63
    const int lc = (tid & 3) << 2;      // 0,4,8,12
    const float* Ag = g_xnorm + (size_t)(bm + lr) * KDIM + lc;
    const float* Bg = W       + (size_t)(bn + lr) * KDIM + lc;

    for (int k0 = 0; k0 < KDIM; k0 += 16) {
        // prefetch into regs, then stage through smem
        float4 pa0 = *(const float4*)(Ag + k0);
        float4 pa1 = *(const float4*)(Ag + k0 + (size_t)64 * KDIM);
        float4 pb0 = *(const float4*)(Bg + k0);
        float4 pb1 = *(const float4*)(Bg + k0 + (size_t)64 * KDIM);
        __syncthreads();
        *(float4*)&As[lr][lc]      = pa0;
        *(float4*)&As[lr + 64][lc] = pa1;
        *(float4*)&Bs[lr][lc]      = pb0;
        *(float4*)&Bs[lr + 64][lc] = pb1;
        __syncthreads();

        #pragma unroll
        for (int kk = 0; kk < 16; kk += 8) {
            uint32_t ahi[4][4], alo[4][4];
            #pragma unroll
            for (int i = 0; i < 4; i++) {
                const int r0 = wm + i * 16 + grp;
                split_tf32(As[r0][kk + tig],         ahi[i][0], alo[i][0]);
                split_tf32(As[r0 + 8][kk + tig],     ahi[i][1], alo[i][1]);
                split_tf32(As[r0][kk + tig + 4],     ahi[i][2], alo[i][2]);
                split_tf32(As[r0 + 8][kk + tig + 4], ahi[i][3], alo[i][3]);
            }
            uint32_t bhi[4][2], blo[4][2];
            #pragma unroll
            for (int j = 0; j < 4; j++) {
                const int r0 = wn + j * 8 + grp;
                split_tf32(Bs[r0][kk + tig],     bhi[j][0], blo[j][0]);
                split_tf32(Bs[r0][kk + tig + 4], bhi[j][1], blo[j][1]);
            }
            #pragma unroll
            for (int i = 0; i < 4; i++)
                #pragma unroll
                for (int j = 0; j < 4; j++) {
                    mma_tf32(acc[i][j], ahi[i], bhi[j]);   // hi*hi
                    mma_tf32(acc[i][j], ahi[i], blo[j]);   // hi*lo
                    mma_tf32(acc[i][j], alo[i], bhi[j]);   // lo*hi
                }
        }
    }

    // Fused epilogue: + bias, activation, store into g_ufr [M][3D]
    #pragma unroll
    for (int i = 0; i < 4; i++) {
        const int rm = bm + wm + i * 16 + grp;
        float* o0 = g_ufr + (size_t)rm * NCOLS;
        float* o1 = g_ufr + (size_t)(rm + 8) * NCOLS;
        #pragma unroll
        for (int j = 0; j < 4; j++) {
            const int cn = bn + wn + j * 8 + 2 * tig;
            const float b0 = bias[cn], b1 = bias[cn + 1];
            o0[cn]     = sru_act(acc[i][j][0] + b0, cn);
            o0[cn + 1] = sru_act(acc[i][j][1] + b1, cn + 1);
            o1[cn]     = sru_act(acc[i][j][2] + b0, cn);
            o1[cn + 1] = sru_act(acc[i][j][3] + b1, cn + 1);
        }
    }
}

// ---------------------------------------------------------------------------
// Kernel 3: sequential scan + gated combine + residual. One thread per (b,d)
// chain (8192 threads). Coalesced over d; unroll for MLP.
// ---------------------------------------------------------------------------
__global__ void __launch_bounds__(256) sru_scan(const float* __restrict__ x,
                                                const float* __restrict__ c0,
                                                float* __restrict__ out) {
    const int idx = blockIdx.x * blockDim.x + threadIdx.x;  // 0..8191
    const int b = idx >> 10;
    const int d = idx & (DIM - 1);
    float c = c0[idx];

    #pragma unroll 4
    for (int l = 0; l < LSEQ; l++) {
        const size_t m = (size_t)l * BATCH + b;
        const float* uf = g_ufr + m * NCOLS;
        const float u  = uf[d];
        const float f  = uf[DIM + d];
        const float r  = uf[2 * DIM + d];
        const float xn = g_xnorm[m * DIM + d];
        const float xv = x[m * DIM + d];
        c = f * c + (1.0f - f) * u;
        const float h = r * tanhf(c) + (1.0f - r) * xn;
        out[m * DIM + d] = xv + h;
    }
    out[(size_t)MROWS * DIM + idx] = c;   // last_c appended after y
}

// ---------------------------------------------------------------------------
extern "C" void kernel_launch(void* const* d_in, const int* in_sizes, int n_in,
                              void* d_out, int out_size) {
    const float* x    = (const float*)d_in[0];
    const float* c    = (const float*)d_in[1];
    const float* W    = (const float*)d_in[2];
    const float* b    = (const float*)d_in[3];
    const float* ln_g = (const float*)d_in[4];
    const float* ln_b = (const float*)d_in[5];
    float* out = (float*)d_out;

    sru_ln<<<MROWS, 256>>>(x, ln_g, ln_b);

    dim3 ggrid(NCOLS / 128, MROWS / 128);   // 24 x 128
    sru_gemm<<<ggrid, 256>>>(W, b);

    sru_scan<<<(BATCH * DIM) / 256, 256>>>(x, c, out);
}

// round 5
// speedup vs baseline: 4.1796x; 4.1796x over previous
#include <cuda_runtime.h>
#include <cuda_fp16.h>
#include <cstdint>
#include <math.h>

// Problem dims
#define LSEQ 2048
#define BATCH 8
#define DIM 1024
#define MROWS (LSEQ * BATCH)    // 16384
#define NCOLS (3 * DIM)         // 3072
#define LN_EPS 1e-5f

// fp16 2-term split: A_ext = [hi | lo] (K_ext = 2048), B = [hi] (1024),
// result = (hi_a + lo_a) . hi_b = a . hi_b  (error ~1.4e-4 rel, incoherent)
#define KA 2048
#define KB 1024

// GEMM tiling
#define BM 128
#define BN 256
#define BK 64                   // fp16 per chunk = 128 bytes/row
#define NCH (KA / BK)           // 32 chunks
#define STG 3

// Scan chunking
#define SCH 32                  // chunks over L
#define SCL (LSEQ / SCH)        // 64 steps per chunk

// Scratch (device globals; allocation-free)
__device__ __align__(128) __half g_aext[(size_t)MROWS * KA];    // 64 MB
__device__ __align__(128) __half g_bext[(size_t)NCOLS * KB];    // 6 MB
__device__ __align__(128) float  g_ufr [(size_t)MROWS * NCOLS]; // 192 MB
__device__ float g_P  [SCH * BATCH * DIM];                      // 1 MB
__device__ float g_q  [SCH * BATCH * DIM];                      // 1 MB
__device__ float g_cin[SCH * BATCH * DIM];                      // 1 MB

// ---------------------------------------------------------------------------
// Fast activations (HW MUFU, ~1e-6 err)
// ---------------------------------------------------------------------------
__device__ __forceinline__ float fsigmoid(float x) {
    float e = __expf(-x);
    float r; asm("rcp.approx.f32 %0, %1;" : "=f"(r) : "f"(1.0f + e));
    return r;
}
__device__ __forceinline__ float ftanh(float x) {
    float e = __expf(-2.0f * x);
    float r; asm("rcp.approx.f32 %0, %1;" : "=f"(r) : "f"(1.0f + e));
    return 2.0f * r - 1.0f;
}

// ---------------------------------------------------------------------------
// Kernel 1: LayerNorm -> fp16 hi/lo split, A_ext = [hi | lo]
// ---------------------------------------------------------------------------
__global__ void __launch_bounds__(256) sru_ln(const float* __restrict__ x,
                                              const float* __restrict__ ln_g,
                                              const float* __restrict__ ln_b) {
    __shared__ float red_s[8], red_ss[8];
    const int row = blockIdx.x;
    const int t = threadIdx.x;

    float4 a = ((const float4*)(x + (size_t)row * DIM))[t];
    float s  = a.x + a.y + a.z + a.w;
    float ss = a.x * a.x + a.y * a.y + a.z * a.z + a.w * a.w;
    #pragma unroll
    for (int o = 16; o > 0; o >>= 1) {
        s  += __shfl_xor_sync(0xFFFFFFFFu, s, o);
        ss += __shfl_xor_sync(0xFFFFFFFFu, ss, o);
    }
    if ((t & 31) == 0) { red_s[t >> 5] = s; red_ss[t >> 5] = ss; }
    __syncthreads();
    float ts = 0.f, tss = 0.f;
    #pragma unroll
    for (int i = 0; i < 8; i++) { ts += red_s[i]; tss += red_ss[i]; }

    const float mu   = ts * (1.0f / DIM);
    const float var  = tss * (1.0f / DIM) - mu * mu;
    const float rstd = rsqrtf(var + LN_EPS);

    float4 g = ((const float4*)ln_g)[t];
    float4 b = ((const float4*)ln_b)[t];
    float o[4];
    o[0] = (a.x - mu) * rstd * g.x + b.x;
    o[1] = (a.y - mu) * rstd * g.y + b.y;
    o[2] = (a.z - mu) * rstd * g.z + b.z;
    o[3] = (a.w - mu) * rstd * g.w + b.w;

    union { __half v[4]; uint2 u; } H, L;
    #pragma unroll
    for (int i = 0; i < 4; i++) {
        H.v[i] = __float2half_rn(o[i]);
        L.v[i] = __float2half_rn(o[i] - __half2float(H.v[i]));
    }
    __half* rowp = g_aext + (size_t)row * KA;
    ((uint2*)(rowp))[t]       = H.u;   // seg0: hi
    ((uint2*)(rowp + DIM))[t] = L.u;   // seg1: lo
}

// ---------------------------------------------------------------------------
// Kernel 1b: W -> fp16 hi
// ---------------------------------------------------------------------------
__global__ void __launch_bounds__(256) sru_wsplit(const float* __restrict__ W) {
    const int t = blockIdx.x * 256 + threadIdx.x;   // 0..786431
    const int row = t >> 8;                         // 0..3071
    const int c4  = t & 255;
    float4 v = ((const float4*)(W + (size_t)row * DIM))[c4];
    float o[4] = {v.x, v.y, v.z, v.w};
    union { __half v[4]; uint2 u; } H;
    #pragma unroll
    for (int i = 0; i < 4; i++) H.v[i] = __float2half_rn(o[i]);
    ((uint2*)(g_bext + (size_t)row * KB))[c4] = H.u;
}

// ---------------------------------------------------------------------------
// Kernel 2: HMMA GEMM (mma.sync m16n8k16 f16->f32), fused bias+activation.
// BM=128 x BN=256 x BK=64, 256 thr (8 warps: 2M x 4N, warp tile 64x64),
// 3-stage cp.async pipeline, XOR-swizzled smem, conflict-free ldmatrix.
// ---------------------------------------------------------------------------
#define ASTG_BYTES (BM * 128)            // 16 KB
#define BSTG_BYTES (BN * 128)            // 32 KB
#define STG_BYTES  (ASTG_BYTES + BSTG_BYTES)
#define SMEM_GEMM  (STG * STG_BYTES)     // 144 KB

__device__ __forceinline__ void cp_async16(uint32_t dst, const void* src) {
    asm volatile("cp.async.cg.shared.global [%0], [%1], 16;" :: "r"(dst), "l"(src));
}
__device__ __forceinline__ void ldsm_x4(uint32_t& r0, uint32_t& r1, uint32_t& r2,
                                        uint32_t& r3, uint32_t addr) {
    asm volatile("ldmatrix.sync.aligned.m8n8.x4.shared.b16 {%0,%1,%2,%3}, [%4];"
                 : "=r"(r0), "=r"(r1), "=r"(r2), "=r"(r3) : "r"(addr));
}
__device__ __forceinline__ void mma16816(float* d, const uint32_t* a,
                                         const uint32_t* b) {
    asm volatile(
        "mma.sync.aligned.m16n8k16.row.col.f32.f16.f16.f32 "
        "{%0,%1,%2,%3}, {%4,%5,%6,%7}, {%8,%9}, {%0,%1,%2,%3};"
        : "+f"(d[0]), "+f"(d[1]), "+f"(d[2]), "+f"(d[3])
        : "r"(a[0]), "r"(a[1]), "r"(a[2]), "r"(a[3]), "r"(b[0]), "r"(b[1]));
}

__global__ void __launch_bounds__(256, 1) sru_gemm_hmma(const float* __restrict__ bias) {
    extern __shared__ char smem[];
    const uint32_t sbase = (uint32_t)__cvta_generic_to_shared(smem);
    const int tid  = threadIdx.x;
    const int lane = tid & 31;
    const int warp = tid >> 5;
    const int wm   = (warp >> 2) * 64;      // 0 / 64
    const int wn   = (warp & 3) * 64;       // 0..192
    const int bm   = blockIdx.y * BM;
    const int bn   = blockIdx.x * BN;

    float acc[4][8][4];
    #pragma unroll
    for (int i = 0; i < 4; i++)
        #pragma unroll
        for (int j = 0; j < 8; j++)
            #pragma unroll
            for (int e = 0; e < 4; e++) acc[i][j][e] = 0.0f;

    // cp.async staging: A 1024 16B-units (4/thr), B 2048 (8/thr)
    const int ar = (tid + 0 * 256) >> 3;  // base rows; pattern repeats +32 rows
    const int aj = tid & 7;

    auto load_stage = [&](int c, int buf) {
        const uint32_t sA = sbase + buf * STG_BYTES;
        const uint32_t sB = sA + ASTG_BYTES;
        #pragma unroll
        for (int i = 0; i < 4; i++) {
            const int u = tid + i * 256;
            const int r = u >> 3, j = u & 7;
            const __half* src = g_aext + (size_t)(bm + r) * KA + c * BK + j * 8;
            cp_async16(sA + r * 128 + ((j ^ (r & 7)) << 4), src);
        }
        const int cb = c & 15;   // B has only 16 chunks (K=1024), reused for lo half
        #pragma unroll
        for (int i = 0; i < 8; i++) {
            const int u = tid + i * 256;
            const int r = u >> 3, j = u & 7;
            const __half* src = g_bext + (size_t)(bn + r) * KB + cb * BK + j * 8;
            cp_async16(sB + r * 128 + ((j ^ (r & 7)) << 4), src);
        }
    };

    load_stage(0, 0);
    asm volatile("cp.async.commit_group;");
    load_stage(1, 1);
    asm volatile("cp.async.commit_group;");

    // per-lane ldmatrix row/chunk components
    const int aRow = ((lane >> 3) & 1) * 8 + (lane & 7);   // + wm + i*16
    const int aJ   = (lane >> 4);                          // + 2s
    const int bRow = ((lane >> 4) & 1) * 8 + (lane & 7);   // + wn + p*16
    const int bJ   = (lane >> 3) & 1;                      // + 2s

    for (int c = 0; c < NCH; c++) {
        asm volatile("cp.async.wait_group 1;");
        __syncthreads();
        if (c + 2 < NCH) load_stage(c + 2, (c + 2) % STG);
        asm volatile("cp.async.commit_group;");

        const int buf = c % STG;
        const uint32_t sA = sbase + buf * STG_BYTES;
        const uint32_t sB = sA + ASTG_BYTES;

        #pragma unroll
        for (int s = 0; s < 4; s++) {
            uint32_t af[4][4];
            #pragma unroll
            for (int i = 0; i < 4; i++) {
                const int r = wm + i * 16 + aRow;
                const int j = 2 * s + aJ;
                ldsm_x4(af[i][0], af[i][1], af[i][2], af[i][3],
                        sA + r * 128 + (((j ^ (r & 7))) << 4));
            }
            uint32_t bf[4][4];
            #pragma unroll
            for (int p = 0; p < 4; p++) {
                const int r = wn + p * 16 + bRow;
                const int j = 2 * s + bJ;
                ldsm_x4(bf[p][0], bf[p][1], bf[p][2], bf[p][3],
                        sB + r * 128 + (((j ^ (r & 7))) << 4));
            }
            #pragma unroll
            for (int i = 0; i < 4; i++)
                #pragma unroll
                for (int p = 0; p < 4; p++) {
                    mma16816(acc[i][2 * p],     af[i], &bf[p][0]);
                    mma16816(acc[i][2 * p + 1], af[i], &bf[p][2]);
                }
        }
    }

    // Epilogue: bias + activation, direct float2 stores
    const bool is_u = (bn < DIM);
    const int mrow0 = bm + wm + (lane >> 2);
    const int ncol0 = bn + wn + 2 * (lane & 3);
    #pragma unroll
    for (int j = 0; j < 8; j++) {
        const int n = ncol0 + j * 8;
        const float2 b2 = *(const float2*)&bias[n];
        #pragma unroll
        for (int i = 0; i < 4; i++) {
            const int m0 = mrow0 + i * 16;
            float v0 = acc[i][j][0] + b2.x;
            float v1 = acc[i][j][1] + b2.y;
            float v2 = acc[i][j][2] + b2.x;
            float v3 = acc[i][j][3] + b2.y;
            float2 o0, o1;
            if (is_u) { o0 = {ftanh(v0), ftanh(v1)};       o1 = {ftanh(v2), ftanh(v3)}; }
            else      { o0 = {fsigmoid(v0), fsigmoid(v1)}; o1 = {fsigmoid(v2), fsigmoid(v3)}; }
            *(float2*)&g_ufr[(size_t)m0 * NCOLS + n]       = o0;
            *(float2*)&g_ufr[(size_t)(m0 + 8) * NCOLS + n] = o1;
        }
    }
}

// ---------------------------------------------------------------------------
// Kernel 3a: per-chunk (P, q): c_out = P*c_in + q over SCL steps
// ---------------------------------------------------------------------------
__global__ void __launch_bounds__(256) sru_scanA() {
    const int idx = blockIdx.x * 256 + threadIdx.x;   // 0..262143
    const int chunk = idx >> 13;
    const int r     = idx & 8191;
    const int b     = r >> 10;
    const int d     = r & (DIM - 1);
    const int m0 = chunk * SCL * BATCH + b;

    float P = 1.0f, q = 0.0f;
    #pragma unroll 4
    for (int s = 0; s < SCL; s++) {
        const size_t m = (size_t)(m0 + s * BATCH);
        const float* uf = g_ufr + m * NCOLS;
        const float u = uf[d];
        const float f = uf[DIM + d];
        q = f * q + (1.0f - f) * u;
        P *= f;
    }
    g_P[idx] = P;
    g_q[idx] = q;
}

// ---------------------------------------------------------------------------
// Kernel 3b: combine chunk transforms serially (32 steps), emit chunk c_in
// ---------------------------------------------------------------------------
__global__ void __launch_bounds__(256) sru_scanB(const float* __restrict__ c0,
                                                 float* __restrict__ out) {
    const int idx = blockIdx.x * 256 + threadIdx.x;   // 0..8191
    float c = c0[idx];
    #pragma unroll
    for (int k = 0; k < SCH; k++) {
        g_cin[k * 8192 + idx] = c;
        c = g_P[k * 8192 + idx] * c + g_q[k * 8192 + idx];
    }
    out[(size_t)MROWS * DIM + idx] = c;   // last_c
}

// ---------------------------------------------------------------------------
// Kernel 3c: re-scan chunks with true c_in; gated combine + residual
// ---------------------------------------------------------------------------
__global__ void __launch_bounds__(256) sru_scanC(const float* __restrict__ x,
                                                 float* __restrict__ out) {
    const int idx = blockIdx.x * 256 + threadIdx.x;
    const int chunk = idx >> 13;
    const int r     = idx & 8191;
    const int b     = r >> 10;
    const int d     = r & (DIM - 1);
    const int m0 = chunk * SCL * BATCH + b;

    float c = g_cin[chunk * 8192 + r];
    #pragma unroll 4
    for (int s = 0; s < SCL; s++) {
        const size_t m = (size_t)(m0 + s * BATCH);
        const float* uf = g_ufr + m * NCOLS;
        const float u  = uf[d];
        const float f  = uf[DIM + d];
        const float rg = uf[2 * DIM + d];
        const __half* ax = g_aext + m * KA + d;
        const float xn = __half2float(ax[0]) + __half2float(ax[DIM]);
        const float xv = x[m * DIM + d];
        c = f * c + (1.0f - f) * u;
        const float h = rg * ftanh(c) + (1.0f - rg) * xn;
        out[m * DIM + d] = xv + h;
    }
}

// ---------------------------------------------------------------------------
extern "C" void kernel_launch(void* const* d_in, const int* in_sizes, int n_in,
                              void* d_out, int out_size) {
    const float* x    = (const float*)d_in[0];
    const float* c    = (const float*)d_in[1];
    const float* W    = (const float*)d_in[2];
    const float* b    = (const float*)d_in[3];
    const float* ln_g = (const float*)d_in[4];
    const float* ln_b = (const float*)d_in[5];
    float* out = (float*)d_out;

    cudaFuncSetAttribute(sru_gemm_hmma, cudaFuncAttributeMaxDynamicSharedMemorySize,
                         SMEM_GEMM);

    sru_ln<<<MROWS, 256>>>(x, ln_g, ln_b);
    sru_wsplit<<<NCOLS, 256>>>(W);

    dim3 ggrid(NCOLS / BN, MROWS / BM);   // 12 x 128
    sru_gemm_hmma<<<ggrid, 256, SMEM_GEMM>>>(b);

    sru_scanA<<<(SCH * BATCH * DIM) / 256, 256>>>();
    sru_scanB<<<(BATCH * DIM) / 256, 256>>>(c, out);
    sru_scanC<<<(SCH * BATCH * DIM) / 256, 256>>>(x, out);
}

// round 6
// speedup vs baseline: 6.5551x; 1.5684x over previous
#include <cuda_runtime.h>
#include <cuda_fp16.h>
#include <cstdint>
#include <math.h>

// Problem dims
#define LSEQ 2048
#define BATCH 8
#define DIM 1024
#define MROWS (LSEQ * BATCH)    // 16384
#define NCOLS (3 * DIM)         // 3072
#define LN_EPS 1e-5f

// A stored as [hi | lo] fp16 (lo used only for xn reconstruction in scan).
// GEMM computes a_hi . b_hi only (K = 1024); dropped terms ~4-5e-4 rel.
#define KA 2048
#define KB 1024

// GEMM tiling
#define BM 128
#define BN 256
#define BK 64                   // fp16 per chunk = 128 bytes/row
#define NCH (KB / BK)           // 16 chunks
#define STG 3

// Scan chunking
#define SCH 32
#define SCL (LSEQ / SCH)        // 64

// Scratch
__device__ __align__(128) __half g_aext[(size_t)MROWS * KA];    // 64 MB
__device__ __align__(128) __half g_bext[(size_t)NCOLS * KB];    // 6 MB
__device__ __align__(128) float  g_ufr [(size_t)MROWS * NCOLS]; // 192 MB
__device__ float g_P  [SCH * BATCH * DIM];
__device__ float g_q  [SCH * BATCH * DIM];
__device__ float g_cin[SCH * BATCH * DIM];

// ---------------------------------------------------------------------------
__device__ __forceinline__ float fsigmoid(float x) {
    float e = __expf(-x);
    float r; asm("rcp.approx.f32 %0, %1;" : "=f"(r) : "f"(1.0f + e));
    return r;
}
__device__ __forceinline__ float ftanh(float x) {
    float e = __expf(-2.0f * x);
    float r; asm("rcp.approx.f32 %0, %1;" : "=f"(r) : "f"(1.0f + e));
    return 2.0f * r - 1.0f;
}

// ---------------------------------------------------------------------------
// Kernel 1 (merged): blocks [0, MROWS) do LayerNorm->fp16 hi/lo split;
// blocks [MROWS, MROWS+NCOLS) do W->fp16.
// ---------------------------------------------------------------------------
__global__ void __launch_bounds__(256) sru_prep(const float* __restrict__ x,
                                                const float* __restrict__ ln_g,
                                                const float* __restrict__ ln_b,
                                                const float* __restrict__ W) {
    __shared__ float red_s[8], red_ss[8];
    const int t = threadIdx.x;

    if (blockIdx.x < MROWS) {
        const int row = blockIdx.x;
        float4 a = ((const float4*)(x + (size_t)row * DIM))[t];
        float s  = a.x + a.y + a.z + a.w;
        float ss = a.x * a.x + a.y * a.y + a.z * a.z + a.w * a.w;
        #pragma unroll
        for (int o = 16; o > 0; o >>= 1) {
            s  += __shfl_xor_sync(0xFFFFFFFFu, s, o);
            ss += __shfl_xor_sync(0xFFFFFFFFu, ss, o);
        }
        if ((t & 31) == 0) { red_s[t >> 5] = s; red_ss[t >> 5] = ss; }
        __syncthreads();
        float ts = 0.f, tss = 0.f;
        #pragma unroll
        for (int i = 0; i < 8; i++) { ts += red_s[i]; tss += red_ss[i]; }

        const float mu   = ts * (1.0f / DIM);
        const float var  = tss * (1.0f / DIM) - mu * mu;
        const float rstd = rsqrtf(var + LN_EPS);

        float4 g = ((const float4*)ln_g)[t];
        float4 b = ((const float4*)ln_b)[t];
        float o[4];
        o[0] = (a.x - mu) * rstd * g.x + b.x;
        o[1] = (a.y - mu) * rstd * g.y + b.y;
        o[2] = (a.z - mu) * rstd * g.z + b.z;
        o[3] = (a.w - mu) * rstd * g.w + b.w;

        union { __half v[4]; uint2 u; } H, L;
        #pragma unroll
        for (int i = 0; i < 4; i++) {
            H.v[i] = __float2half_rn(o[i]);
            L.v[i] = __float2half_rn(o[i] - __half2float(H.v[i]));
        }
        __half* rowp = g_aext + (size_t)row * KA;
        ((uint2*)(rowp))[t]       = H.u;   // hi (GEMM + xn)
        ((uint2*)(rowp + DIM))[t] = L.u;   // lo (xn only)
    } else {
        const int u = (blockIdx.x - MROWS) * 256 + t;  // 0..786431
        const int row = u >> 8;
        const int c4  = u & 255;
        float4 v = ((const float4*)(W + (size_t)row * DIM))[c4];
        float o[4] = {v.x, v.y, v.z, v.w};
        union { __half v[4]; uint2 u2; } H;
        #pragma unroll
        for (int i = 0; i < 4; i++) H.v[i] = __float2half_rn(o[i]);
        ((uint2*)(g_bext + (size_t)row * KB))[c4] = H.u2;
    }
}

// ---------------------------------------------------------------------------
// Kernel 2: HMMA GEMM (m16n8k16 f16->f32), K=1024, fused bias+activation.
// ---------------------------------------------------------------------------
#define ASTG_BYTES (BM * 128)            // 16 KB
#define BSTG_BYTES (BN * 128)            // 32 KB
#define STG_BYTES  (ASTG_BYTES + BSTG_BYTES)
#define SMEM_GEMM  (STG * STG_BYTES)     // 144 KB

__device__ __forceinline__ void cp_async16(uint32_t dst, const void* src) {
    asm volatile("cp.async.cg.shared.global [%0], [%1], 16;" :: "r"(dst), "l"(src));
}
__device__ __forceinline__ void ldsm_x4(uint32_t& r0, uint32_t& r1, uint32_t& r2,
                                        uint32_t& r3, uint32_t addr) {
    asm volatile("ldmatrix.sync.aligned.m8n8.x4.shared.b16 {%0,%1,%2,%3}, [%4];"
                 : "=r"(r0), "=r"(r1), "=r"(r2), "=r"(r3) : "r"(addr));
}
__device__ __forceinline__ void mma16816(float* d, const uint32_t* a,
                                         const uint32_t* b) {
    asm volatile(
        "mma.sync.aligned.m16n8k16.row.col.f32.f16.f16.f32 "
        "{%0,%1,%2,%3}, {%4,%5,%6,%7}, {%8,%9}, {%0,%1,%2,%3};"
        : "+f"(d[0]), "+f"(d[1]), "+f"(d[2]), "+f"(d[3])
        : "r"(a[0]), "r"(a[1]), "r"(a[2]), "r"(a[3]), "r"(b[0]), "r"(b[1]));
}

__global__ void __launch_bounds__(256, 1) sru_gemm_hmma(const float* __restrict__ bias) {
    extern __shared__ char smem[];
    const uint32_t sbase = (uint32_t)__cvta_generic_to_shared(smem);
    const int tid  = threadIdx.x;
    const int lane = tid & 31;
    const int warp = tid >> 5;
    const int wm   = (warp >> 2) * 64;
    const int wn   = (warp & 3) * 64;
    const int bm   = blockIdx.y * BM;
    const int bn   = blockIdx.x * BN;

    float acc[4][8][4];
    #pragma unroll
    for (int i = 0; i < 4; i++)
        #pragma unroll
        for (int j = 0; j < 8; j++)
            #pragma unroll
            for (int e = 0; e < 4; e++) acc[i][j][e] = 0.0f;

    auto load_stage = [&](int c, int buf) {
        const uint32_t sA = sbase + buf * STG_BYTES;
        const uint32_t sB = sA + ASTG_BYTES;
        #pragma unroll
        for (int i = 0; i < 4; i++) {
            const int u = tid + i * 256;
            const int r = u >> 3, j = u & 7;
            const __half* src = g_aext + (size_t)(bm + r) * KA + c * BK + j * 8;
            cp_async16(sA + r * 128 + ((j ^ (r & 7)) << 4), src);
        }
        #pragma unroll
        for (int i = 0; i < 8; i++) {
            const int u = tid + i * 256;
            const int r = u >> 3, j = u & 7;
            const __half* src = g_bext + (size_t)(bn + r) * KB + c * BK + j * 8;
            cp_async16(sB + r * 128 + ((j ^ (r & 7)) << 4), src);
        }
    };

    load_stage(0, 0);
    asm volatile("cp.async.commit_group;");
    load_stage(1, 1);
    asm volatile("cp.async.commit_group;");

    const int aRow = ((lane >> 3) & 1) * 8 + (lane & 7);
    const int aJ   = (lane >> 4);
    const int bRow = ((lane >> 4) & 1) * 8 + (lane & 7);
    const int bJ   = (lane >> 3) & 1;

    for (int c = 0; c < NCH; c++) {
        asm volatile("cp.async.wait_group 1;");
        __syncthreads();
        if (c + 2 < NCH) load_stage(c + 2, (c + 2) % STG);
        asm volatile("cp.async.commit_group;");

        const int buf = c % STG;
        const uint32_t sA = sbase + buf * STG_BYTES;
        const uint32_t sB = sA + ASTG_BYTES;

        #pragma unroll
        for (int s = 0; s < 4; s++) {
            uint32_t af[4][4];
            #pragma unroll
            for (int i = 0; i < 4; i++) {
                const int r = wm + i * 16 + aRow;
                const int j = 2 * s + aJ;
                ldsm_x4(af[i][0], af[i][1], af[i][2], af[i][3],
                        sA + r * 128 + ((j ^ (r & 7)) << 4));
            }
            uint32_t bf[4][4];
            #pragma unroll
            for (int p = 0; p < 4; p++) {
                const int r = wn + p * 16 + bRow;
                const int j = 2 * s + bJ;
                ldsm_x4(bf[p][0], bf[p][1], bf[p][2], bf[p][3],
                        sB + r * 128 + ((j ^ (r & 7)) << 4));
            }
            #pragma unroll
            for (int i = 0; i < 4; i++)
                #pragma unroll
                for (int p = 0; p < 4; p++) {
                    mma16816(acc[i][2 * p],     af[i], &bf[p][0]);
                    mma16816(acc[i][2 * p + 1], af[i], &bf[p][2]);
                }
        }
    }

    const bool is_u = (bn < DIM);
    const int mrow0 = bm + wm + (lane >> 2);
    const int ncol0 = bn + wn + 2 * (lane & 3);
    #pragma unroll
    for (int j = 0; j < 8; j++) {
        const int n = ncol0 + j * 8;
        const float2 b2 = *(const float2*)&bias[n];
        #pragma unroll
        for (int i = 0; i < 4; i++) {
            const int m0 = mrow0 + i * 16;
            float v0 = acc[i][j][0] + b2.x;
            float v1 = acc[i][j][1] + b2.y;
            float v2 = acc[i][j][2] + b2.x;
            float v3 = acc[i][j][3] + b2.y;
            float2 o0, o1;
            if (is_u) { o0 = {ftanh(v0), ftanh(v1)};       o1 = {ftanh(v2), ftanh(v3)}; }
            else      { o0 = {fsigmoid(v0), fsigmoid(v1)}; o1 = {fsigmoid(v2), fsigmoid(v3)}; }
            *(float2*)&g_ufr[(size_t)m0 * NCOLS + n]       = o0;
            *(float2*)&g_ufr[(size_t)(m0 + 8) * NCOLS + n] = o1;
        }
    }
}

// ---------------------------------------------------------------------------
// Kernel 3a: per-chunk (P, q)
// ---------------------------------------------------------------------------
__global__ void __launch_bounds__(256) sru_scanA() {
    const int idx = blockIdx.x * 256 + threadIdx.x;
    const int chunk = idx >> 13;
    const int r     = idx & 8191;
    const int b     = r >> 10;
    const int d     = r & (DIM - 1);
    const int m0 = chunk * SCL * BATCH + b;

    float P = 1.0f, q = 0.0f;
    #pragma unroll 4
    for (int s = 0; s < SCL; s++) {
        const size_t m = (size_t)(m0 + s * BATCH);
        const float* uf = g_ufr + m * NCOLS;
        const float u = uf[d];
        const float f = uf[DIM + d];
        q = f * q + (1.0f - f) * u;
        P *= f;
    }
    g_P[idx] = P;
    g_q[idx] = q;
}

// ---------------------------------------------------------------------------
// Kernel 3b: serial chunk combine
// ---------------------------------------------------------------------------
__global__ void __launch_bounds__(256) sru_scanB(const float* __restrict__ c0,
                                                 float* __restrict__ out) {
    const int idx = blockIdx.x * 256 + threadIdx.x;
    float c = c0[idx];
    #pragma unroll
    for (int k = 0; k < SCH; k++) {
        g_cin[k * 8192 + idx] = c;
        c = g_P[k * 8192 + idx] * c + g_q[k * 8192 + idx];
    }
    out[(size_t)MROWS * DIM + idx] = c;
}

// ---------------------------------------------------------------------------
// Kernel 3c: re-scan with true c_in; gated combine + residual
// ---------------------------------------------------------------------------
__global__ void __launch_bounds__(256) sru_scanC(const float* __restrict__ x,
                                                 float* __restrict__ out) {
    const int idx = blockIdx.x * 256 + threadIdx.x;
    const int chunk = idx >> 13;
    const int r     = idx & 8191;
    const int b     = r >> 10;
    const int d     = r & (DIM - 1);
    const int m0 = chunk * SCL * BATCH + b;

    float c = g_cin[chunk * 8192 + r];
    #pragma unroll 4
    for (int s = 0; s < SCL; s++) {
        const size_t m = (size_t)(m0 + s * BATCH);
        const float* uf = g_ufr + m * NCOLS;
        const float u  = uf[d];
        const float f  = uf[DIM + d];
        const float rg = uf[2 * DIM + d];
        const __half* ax = g_aext + m * KA + d;
        const float xn = __half2float(ax[0]) + __half2float(ax[DIM]);
        const float xv = x[m * DIM + d];
        c = f * c + (1.0f - f) * u;
        const float h = rg * ftanh(c) + (1.0f - rg) * xn;
        out[m * DIM + d] = xv + h;
    }
}

// ---------------------------------------------------------------------------
extern "C" void kernel_launch(void* const* d_in, const int* in_sizes, int n_in,
                              void* d_out, int out_size) {
    const float* x    = (const float*)d_in[0];
    const float* c    = (const float*)d_in[1];
    const float* W    = (const float*)d_in[2];
    const float* b    = (const float*)d_in[3];
    const float* ln_g = (const float*)d_in[4];
    const float* ln_b = (const float*)d_in[5];
    float* out = (float*)d_out;

    cudaFuncSetAttribute(sru_gemm_hmma, cudaFuncAttributeMaxDynamicSharedMemorySize,
                         SMEM_GEMM);

    sru_prep<<<MROWS + NCOLS, 256>>>(x, ln_g, ln_b, W);

    dim3 ggrid(NCOLS / BN, MROWS / BM);   // 12 x 128
    sru_gemm_hmma<<<ggrid, 256, SMEM_GEMM>>>(b);

    sru_scanA<<<(SCH * BATCH * DIM) / 256, 256>>>();
    sru_scanB<<<(BATCH * DIM) / 256, 256>>>(c, out);
    sru_scanC<<<(SCH * BATCH * DIM) / 256, 256>>>(x, out);
}

// round 7
// speedup vs baseline: 6.8140x; 1.0395x over previous
#include <cuda_runtime.h>
#include <cuda_fp16.h>
#include <cstdint>
#include <math.h>

// Problem dims
#define LSEQ 2048
#define BATCH 8
#define DIM 1024
#define MROWS (LSEQ * BATCH)    // 16384
#define NCOLS (3 * DIM)         // 3072
#define LN_EPS 1e-5f

#define KA 2048                 // A stored [hi | lo] fp16 (lo only for xn)
#define KB 1024

// GEMM tiling
#define BM 128
#define BN 256
#define BK 64
#define NCH (KB / BK)           // 16
#define STG 3

// Scan chunking
#define SCH 32
#define SCL (LSEQ / SCH)        // 64

// Scratch
__device__ __align__(128) __half g_aext[(size_t)MROWS * KA];   // 64 MB
__device__ __align__(128) __half g_bext[(size_t)NCOLS * KB];   // 6 MB
__device__ __align__(128) __half g_u[(size_t)MROWS * DIM];     // 32 MB
__device__ __align__(128) __half g_f[(size_t)MROWS * DIM];     // 32 MB
__device__ __align__(128) __half g_r[(size_t)MROWS * DIM];     // 32 MB
__device__ float g_P  [SCH * BATCH * DIM];
__device__ float g_q  [SCH * BATCH * DIM];
__device__ float g_cin[SCH * BATCH * DIM];

// ---------------------------------------------------------------------------
__device__ __forceinline__ float fsigmoid(float x) {
    float e = __expf(-x);
    float r; asm("rcp.approx.f32 %0, %1;" : "=f"(r) : "f"(1.0f + e));
    return r;
}
__device__ __forceinline__ float ftanh(float x) {
    float e = __expf(-2.0f * x);
    float r; asm("rcp.approx.f32 %0, %1;" : "=f"(r) : "f"(1.0f + e));
    return 2.0f * r - 1.0f;
}

// ---------------------------------------------------------------------------
// Kernel 1 (merged): LN -> fp16 hi/lo split; W -> fp16
// ---------------------------------------------------------------------------
__global__ void __launch_bounds__(256) sru_prep(const float* __restrict__ x,
                                                const float* __restrict__ ln_g,
                                                const float* __restrict__ ln_b,
                                                const float* __restrict__ W) {
    __shared__ float red_s[8], red_ss[8];
    const int t = threadIdx.x;

    if (blockIdx.x < MROWS) {
        const int row = blockIdx.x;
        float4 a = ((const float4*)(x + (size_t)row * DIM))[t];
        float s  = a.x + a.y + a.z + a.w;
        float ss = a.x * a.x + a.y * a.y + a.z * a.z + a.w * a.w;
        #pragma unroll
        for (int o = 16; o > 0; o >>= 1) {
            s  += __shfl_xor_sync(0xFFFFFFFFu, s, o);
            ss += __shfl_xor_sync(0xFFFFFFFFu, ss, o);
        }
        if ((t & 31) == 0) { red_s[t >> 5] = s; red_ss[t >> 5] = ss; }
        __syncthreads();
        float ts = 0.f, tss = 0.f;
        #pragma unroll
        for (int i = 0; i < 8; i++) { ts += red_s[i]; tss += red_ss[i]; }

        const float mu   = ts * (1.0f / DIM);
        const float var  = tss * (1.0f / DIM) - mu * mu;
        const float rstd = rsqrtf(var + LN_EPS);

        float4 g = ((const float4*)ln_g)[t];
        float4 b = ((const float4*)ln_b)[t];
        float o[4];
        o[0] = (a.x - mu) * rstd * g.x + b.x;
        o[1] = (a.y - mu) * rstd * g.y + b.y;
        o[2] = (a.z - mu) * rstd * g.z + b.z;
        o[3] = (a.w - mu) * rstd * g.w + b.w;

        union { __half v[4]; uint2 u; } H, L;
        #pragma unroll
        for (int i = 0; i < 4; i++) {
            H.v[i] = __float2half_rn(o[i]);
            L.v[i] = __float2half_rn(o[i] - __half2float(H.v[i]));
        }
        __half* rowp = g_aext + (size_t)row * KA;
        ((uint2*)(rowp))[t]       = H.u;
        ((uint2*)(rowp + DIM))[t] = L.u;
    } else {
        const int u = (blockIdx.x - MROWS) * 256 + t;
        const int row = u >> 8;
        const int c4  = u & 255;
        float4 v = ((const float4*)(W + (size_t)row * DIM))[c4];
        float o[4] = {v.x, v.y, v.z, v.w};
        union { __half v[4]; uint2 u2; } H;
        #pragma unroll
        for (int i = 0; i < 4; i++) H.v[i] = __float2half_rn(o[i]);
        ((uint2*)(g_bext + (size_t)row * KB))[c4] = H.u2;
    }
}

// ---------------------------------------------------------------------------
// Kernel 2: HMMA GEMM (m16n8k16 f16->f32), K=1024, fused bias+act -> fp16 planes
// ---------------------------------------------------------------------------
#define ASTG_BYTES (BM * 128)
#define BSTG_BYTES (BN * 128)
#define STG_BYTES  (ASTG_BYTES + BSTG_BYTES)
#define SMEM_GEMM  (STG * STG_BYTES)     // 144 KB

__device__ __forceinline__ void cp_async16(uint32_t dst, const void* src) {
    asm volatile("cp.async.cg.shared.global [%0], [%1], 16;" :: "r"(dst), "l"(src));
}
__device__ __forceinline__ void ldsm_x4(uint32_t& r0, uint32_t& r1, uint32_t& r2,
                                        uint32_t& r3, uint32_t addr) {
    asm volatile("ldmatrix.sync.aligned.m8n8.x4.shared.b16 {%0,%1,%2,%3}, [%4];"
                 : "=r"(r0), "=r"(r1), "=r"(r2), "=r"(r3) : "r"(addr));
}
__device__ __forceinline__ void mma16816(float* d, const uint32_t* a,
                                         const uint32_t* b) {
    asm volatile(
        "mma.sync.aligned.m16n8k16.row.col.f32.f16.f16.f32 "
        "{%0,%1,%2,%3}, {%4,%5,%6,%7}, {%8,%9}, {%0,%1,%2,%3};"
        : "+f"(d[0]), "+f"(d[1]), "+f"(d[2]), "+f"(d[3])
        : "r"(a[0]), "r"(a[1]), "r"(a[2]), "r"(a[3]), "r"(b[0]), "r"(b[1]));
}

__global__ void __launch_bounds__(256, 1) sru_gemm_hmma(const float* __restrict__ bias) {
    extern __shared__ char smem[];
    const uint32_t sbase = (uint32_t)__cvta_generic_to_shared(smem);
    const int tid  = threadIdx.x;
    const int lane = tid & 31;
    const int warp = tid >> 5;
    const int wm   = (warp >> 2) * 64;
    const int wn   = (warp & 3) * 64;
    const int bm   = blockIdx.y * BM;
    const int bn   = blockIdx.x * BN;

    float acc[4][8][4];
    #pragma unroll
    for (int i = 0; i < 4; i++)
        #pragma unroll
        for (int j = 0; j < 8; j++)
            #pragma unroll
            for (int e = 0; e < 4; e++) acc[i][j][e] = 0.0f;

    auto load_stage = [&](int c, int buf) {
        const uint32_t sA = sbase + buf * STG_BYTES;
        const uint32_t sB = sA + ASTG_BYTES;
        #pragma unroll
        for (int i = 0; i < 4; i++) {
            const int u = tid + i * 256;
            const int r = u >> 3, j = u & 7;
            const __half* src = g_aext + (size_t)(bm + r) * KA + c * BK + j * 8;
            cp_async16(sA + r * 128 + ((j ^ (r & 7)) << 4), src);
        }
        #pragma unroll
        for (int i = 0; i < 8; i++) {
            const int u = tid + i * 256;
            const int r = u >> 3, j = u & 7;
            const __half* src = g_bext + (size_t)(bn + r) * KB + c * BK + j * 8;
            cp_async16(sB + r * 128 + ((j ^ (r & 7)) << 4), src);
        }
    };

    load_stage(0, 0);
    asm volatile("cp.async.commit_group;");
    load_stage(1, 1);
    asm volatile("cp.async.commit_group;");

    const int aRow = ((lane >> 3) & 1) * 8 + (lane & 7);
    const int aJ   = (lane >> 4);
    const int bRow = ((lane >> 4) & 1) * 8 + (lane & 7);
    const int bJ   = (lane >> 3) & 1;

    for (int c = 0; c < NCH; c++) {
        asm volatile("cp.async.wait_group 1;");
        __syncthreads();
        if (c + 2 < NCH) load_stage(c + 2, (c + 2) % STG);
        asm volatile("cp.async.commit_group;");

        const int buf = c % STG;
        const uint32_t sA = sbase + buf * STG_BYTES;
        const uint32_t sB = sA + ASTG_BYTES;

        #pragma unroll
        for (int s = 0; s < 4; s++) {
            uint32_t af[4][4];
            #pragma unroll
            for (int i = 0; i < 4; i++) {
                const int r = wm + i * 16 + aRow;
                const int j = 2 * s + aJ;
                ldsm_x4(af[i][0], af[i][1], af[i][2], af[i][3],
                        sA + r * 128 + ((j ^ (r & 7)) << 4));
            }
            uint32_t bf[4][4];
            #pragma unroll
            for (int p = 0; p < 4; p++) {
                const int r = wn + p * 16 + bRow;
                const int j = 2 * s + bJ;
                ldsm_x4(bf[p][0], bf[p][1], bf[p][2], bf[p][3],
                        sB + r * 128 + ((j ^ (r & 7)) << 4));
            }
            #pragma unroll
            for (int i = 0; i < 4; i++)
                #pragma unroll
                for (int p = 0; p < 4; p++) {
                    mma16816(acc[i][2 * p],     af[i], &bf[p][0]);
                    mma16816(acc[i][2 * p + 1], af[i], &bf[p][2]);
                }
        }
    }

    // Epilogue: bias + activation -> fp16 plane (u / f / r by CTA column range)
    const bool is_u = (bn < DIM);
    __half* plane = is_u ? g_u : ((bn < 2 * DIM) ? g_f : g_r);
    const int mrow0 = bm + wm + (lane >> 2);
    const int ncol0 = bn + wn + 2 * (lane & 3);
    #pragma unroll
    for (int j = 0; j < 8; j++) {
        const int n = ncol0 + j * 8;
        const float2 b2 = *(const float2*)&bias[n];
        const int nc = n & (DIM - 1);
        #pragma unroll
        for (int i = 0; i < 4; i++) {
            const int m0 = mrow0 + i * 16;
            float v0 = acc[i][j][0] + b2.x;
            float v1 = acc[i][j][1] + b2.y;
            float v2 = acc[i][j][2] + b2.x;
            float v3 = acc[i][j][3] + b2.y;
            float2 o0, o1;
            if (is_u) { o0 = {ftanh(v0), ftanh(v1)};       o1 = {ftanh(v2), ftanh(v3)}; }
            else      { o0 = {fsigmoid(v0), fsigmoid(v1)}; o1 = {fsigmoid(v2), fsigmoid(v3)}; }
            *(__half2*)&plane[(size_t)m0 * DIM + nc]       = __floats2half2_rn(o0.x, o0.y);
            *(__half2*)&plane[(size_t)(m0 + 8) * DIM + nc] = __floats2half2_rn(o1.x, o1.y);
        }
    }
}

// ---------------------------------------------------------------------------
// Kernel 3a: per-chunk (P, q); 2 lanes of d per thread (half2)
// ---------------------------------------------------------------------------
__global__ void __launch_bounds__(256) sru_scanA() {
    const int idx = blockIdx.x * 256 + threadIdx.x;   // 0..131071
    const int chunk = idx >> 12;
    const int r     = idx & 4095;
    const int b     = r >> 9;
    const int dh    = r & 511;            // half2 index; d = 2*dh
    const int m0 = chunk * SCL * BATCH + b;

    float2 P = {1.0f, 1.0f}, q = {0.0f, 0.0f};
    #pragma unroll 4
    for (int s = 0; s < SCL; s++) {
        const size_t m = (size_t)(m0 + s * BATCH);
        const float2 u = __half22float2(((const __half2*)(g_u + m * DIM))[dh]);
        const float2 f = __half22float2(((const __half2*)(g_f + m * DIM))[dh]);
        q.x = f.x * q.x + (1.0f - f.x) * u.x;
        q.y = f.y * q.y + (1.0f - f.y) * u.y;
        P.x *= f.x;
        P.y *= f.y;
    }
    const int o = chunk * 8192 + b * DIM + 2 * dh;
    *(float2*)&g_P[o] = P;
    *(float2*)&g_q[o] = q;
}

// ---------------------------------------------------------------------------
// Kernel 3b: serial chunk combine — fully unrolled, loads front-batched
// ---------------------------------------------------------------------------
__global__ void __launch_bounds__(256) sru_scanB(const float* __restrict__ c0,
                                                 float* __restrict__ out) {
    const int idx = blockIdx.x * 256 + threadIdx.x;   // 0..8191
    float P[SCH], q[SCH];
    #pragma unroll
    for (int k = 0; k < SCH; k++) {
        P[k] = g_P[k * 8192 + idx];
        q[k] = g_q[k * 8192 + idx];
    }
    float c = c0[idx];
    #pragma unroll
    for (int k = 0; k < SCH; k++) {
        g_cin[k * 8192 + idx] = c;
        c = P[k] * c + q[k];
    }
    out[(size_t)MROWS * DIM + idx] = c;
}

// ---------------------------------------------------------------------------
// Kernel 3c: re-scan with true c_in; gated combine + residual (2-wide)
// ---------------------------------------------------------------------------
__global__ void __launch_bounds__(256) sru_scanC(const float* __restrict__ x,
                                                 float* __restrict__ out) {
    const int idx = blockIdx.x * 256 + threadIdx.x;
    const int chunk = idx >> 12;
    const int r     = idx & 4095;
    const int b     = r >> 9;
    const int dh    = r & 511;
    const int m0 = chunk * SCL * BATCH + b;

    float2 c = *(const float2*)&g_cin[chunk * 8192 + b * DIM + 2 * dh];
    #pragma unroll 4
    for (int s = 0; s < SCL; s++) {
        const size_t m = (size_t)(m0 + s * BATCH);
        const float2 u  = __half22float2(((const __half2*)(g_u + m * DIM))[dh]);
        const float2 f  = __half22float2(((const __half2*)(g_f + m * DIM))[dh]);
        const float2 rg = __half22float2(((const __half2*)(g_r + m * DIM))[dh]);
        const float2 xh = __half22float2(((const __half2*)(g_aext + m * KA))[dh]);
        const float2 xl = __half22float2(((const __half2*)(g_aext + m * KA + DIM))[dh]);
        const float2 xv = ((const float2*)(x + m * DIM))[dh];
        c.x = f.x * c.x + (1.0f - f.x) * u.x;
        c.y = f.y * c.y + (1.0f - f.y) * u.y;
        float2 o;
        o.x = xv.x + rg.x * ftanh(c.x) + (1.0f - rg.x) * (xh.x + xl.x);
        o.y = xv.y + rg.y * ftanh(c.y) + (1.0f - rg.y) * (xh.y + xl.y);
        ((float2*)(out + m * DIM))[dh] = o;
    }
}

// ---------------------------------------------------------------------------
extern "C" void kernel_launch(void* const* d_in, const int* in_sizes, int n_in,
                              void* d_out, int out_size) {
    const float* x    = (const float*)d_in[0];
    const float* c    = (const float*)d_in[1];
    const float* W    = (const float*)d_in[2];
    const float* b    = (const float*)d_in[3];
    const float* ln_g = (const float*)d_in[4];
    const float* ln_b = (const float*)d_in[5];
    float* out = (float*)d_out;

    cudaFuncSetAttribute(sru_gemm_hmma, cudaFuncAttributeMaxDynamicSharedMemorySize,
                         SMEM_GEMM);

    sru_prep<<<MROWS + NCOLS, 256>>>(x, ln_g, ln_b, W);

    dim3 ggrid(NCOLS / BN, MROWS / BM);
    sru_gemm_hmma<<<ggrid, 256, SMEM_GEMM>>>(b);

    sru_scanA<<<(SCH * BATCH * DIM / 2) / 256, 256>>>();
    sru_scanB<<<(BATCH * DIM) / 256, 256>>>(c, out);
    sru_scanC<<<(SCH * BATCH * DIM / 2) / 256, 256>>>(x, out);
}